// round 15
// baseline (speedup 1.0000x reference)
#include <cuda_runtime.h>
#include <math.h>

#define NB 8
#define NC 12
#define NNtok 785
#define NS 784
#define NH 28
#define ND 768
#define KHID 512
#define PNUM 84
#define SCL 0.7f
#define TPB 1024
#define NWB 32
#define NWA 25                        // warps covering s<784
#define NSUB 8                        // compute sub-blocks per batch
#define NCB (NB * NSUB)               // 64 compute blocks
#define NC4TOT (NB * NS * (ND / 4))   // 1,204,224 float4 (rows 1..784)
#define NCPB (148 - NCB)              // 84 copy blocks -> grid 148 = 1 wave
#define CSTRIDE (NCPB * TPB)          // 86016
#define BROW (NS * (ND / 4))          // 150528 float4 per batch (rows 1..784)
#define ASSIST (NCB * 512 * 4)        // 131072 float4 copied by compute blocks

__device__ __forceinline__ unsigned f2key(float v) {
    unsigned b = __float_as_uint(v);
    return (b & 0x80000000u) ? ~b : (b | 0x80000000u);   // order-preserving
}
// out-index for copy element k over (b, n, d4): layouts differ only by the
// per-batch row-0 skip -> idx = k + (b+1)*192
__device__ __forceinline__ int cidx(int k) {
    return k + (k / BROW + 1) * (ND / 4);
}

__global__ __launch_bounds__(TPB) void kAll(
    const float* __restrict__ x,  const float* __restrict__ w1,
    const float* __restrict__ w2, const float* __restrict__ hs,
    float* __restrict__ out, int seln)
{
    const int tid = threadIdx.x, lane = tid & 31, warp = tid >> 5;

    if (blockIdx.x >= NCB) {
        // ===== copy blocks: hs rows 1..784 -> out (13 rounds: 7 + 6) =======
        const float4* hin = (const float4*)hs;
        float4* o4 = (float4*)out;
        const int base = ASSIST + (blockIdx.x - NCB) * TPB + tid;
        {
            float4 v[7]; int idx[7];
            #pragma unroll
            for (int j = 0; j < 7; j++) {
                int k = base + j * CSTRIDE;          // < NC4TOT for j<7
                idx[j] = cidx(k);
                v[j]   = hin[idx[j]];
            }
            #pragma unroll
            for (int j = 0; j < 7; j++) o4[idx[j]] = v[j];
        }
        {
            float4 v[6]; int idx[6]; bool ok[6];
            #pragma unroll
            for (int j = 0; j < 6; j++) {
                int k = base + (7 + j) * CSTRIDE;
                ok[j] = (k < NC4TOT);
                if (ok[j]) { idx[j] = cidx(k); v[j] = hin[idx[j]]; }
            }
            #pragma unroll
            for (int j = 0; j < 6; j++) if (ok[j]) o4[idx[j]] = v[j];
        }
        return;
    }

    // ============== compute block (b, sub): redundant per-batch stats ======
    __shared__ unsigned      msel[NC][25];      // selection bitmasks
    __shared__ int           hist[NC][256];     // per-channel radix hist
    __shared__ unsigned char whist[NWA][256];   // per-warp conv-value hist
    __shared__ unsigned char c0[NS];
    __shared__ float         msh[NS];
    __shared__ int           sfx[256];
    __shared__ short         spatch[NS];        // patch idx by rank
    __shared__ float         scoef[KHID];       // (u>0?cp:cm)*u
    __shared__ float4        gp4[32 * 24];      // GEMV k-chunk partials
    __shared__ float redf[NWB], redf2[NWB], redf3[NWB], redf4[NWB];
    __shared__ int   redi[NWB];
    __shared__ float s_mean, s_w0, s_w1, s_pa, s_cp, s_cm, s_maxm;
    __shared__ int   s_anchor;

    const int b = blockIdx.x >> 3, sub = blockIdx.x & 7;

    // ---- warps 16-31: copy assist (overlaps the radix phase) -------------
    if (warp >= 16) {
        const float4* hin = (const float4*)hs;
        float4* o4 = (float4*)out;
        const int abase = blockIdx.x * 512 + (tid - 512);
        float4 v[4]; int idx[4];
        #pragma unroll
        for (int r = 0; r < 4; r++) {
            int k = abase + r * (NCB * 512);     // < ASSIST <= NC4TOT
            idx[r] = cidx(k);
            v[r]   = hin[idx[r]];
        }
        #pragma unroll
        for (int r = 0; r < 4; r++) o4[idx[r]] = v[r];
    }

    for (int i = tid; i < NWA * 256 / 4; i += TPB) ((int*)whist)[i] = 0;

    // ---- warp-local top-84: 2 radix passes (16 bits) + exact cleanup -----
    if (warp < NC) {
        const int c = warp;
        const float* row = x + ((long long)(b * NC + c)) * NNtok * NNtok + 1;
        unsigned ukey[25];
        #pragma unroll
        for (int j = 0; j < 25; j++) {
            int s = lane + 32 * j;
            ukey[j] = (s < NS) ? f2key(row[s]) : 0u;   // 0 = smallest key
        }
        unsigned pref = 0u; int rem = PNUM;
        #pragma unroll
        for (int pass = 0; pass < 2; pass++) {
            const int shift = 24 - 8 * pass;
            const unsigned mhi = (pass == 0) ? 0u : 0xFF000000u;
            #pragma unroll
            for (int i = 0; i < 8; i++) hist[c][lane * 8 + i] = 0;
            __syncwarp();
            #pragma unroll
            for (int j = 0; j < 25; j++) {
                unsigned u = ukey[j];
                if ((lane + 32 * j < NS) && (u & mhi) == pref)
                    atomicAdd(&hist[c][(u >> shift) & 255u], 1);
            }
            __syncwarp();
            int hh[8], S = 0;
            #pragma unroll
            for (int i = 0; i < 8; i++) { hh[i] = hist[c][lane * 8 + i]; S += hh[i]; }
            int s = S;                                 // suffix over lanes
            #pragma unroll
            for (int o = 1; o < 32; o <<= 1) {
                int n = __shfl_down_sync(0xFFFFFFFFu, s, o);
                if (lane + o < 32) s += n;
            }
            int run = s - S;                           // sum over lanes > me
            int fbin = -1, fgt = 0;
            #pragma unroll
            for (int i = 7; i >= 0; i--) {
                int gt = run;                          // # keys strictly greater
                if (gt < rem && gt + hh[i] >= rem) { fbin = lane * 8 + i; fgt = gt; }
                run += hh[i];
            }
            unsigned fm = __ballot_sync(0xFFFFFFFFu, fbin >= 0);
            int src = __ffs(fm) - 1;
            int bin = __shfl_sync(0xFFFFFFFFu, fbin, src);
            int gt  = __shfl_sync(0xFFFFFFFFu, fgt, src);
            pref |= ((unsigned)bin) << shift;
            rem  -= gt;
            __syncwarp();
        }
        // cleanup: exact rem-th largest among keys with 16-bit prefix `pref`
        const unsigned p16 = pref >> 16;
        unsigned bound = 0xFFFFFFFFu;
        unsigned T = 0u; int need = rem, cntT = 0;
        while (true) {
            unsigned mymax = 0u;
            #pragma unroll
            for (int j = 0; j < 25; j++) {
                unsigned u = ukey[j];
                if ((lane + 32 * j < NS) && (u >> 16) == p16 && u <= bound)
                    mymax = mymax > u ? mymax : u;
            }
            #pragma unroll
            for (int o = 16; o; o >>= 1) {
                unsigned ov = __shfl_xor_sync(0xFFFFFFFFu, mymax, o);
                mymax = mymax > ov ? mymax : ov;
            }
            int cnt = 0;
            #pragma unroll
            for (int j = 0; j < 25; j++)
                cnt += ((lane + 32 * j < NS) && ukey[j] == mymax) ? 1 : 0;
            #pragma unroll
            for (int o = 16; o; o >>= 1)
                cnt += __shfl_xor_sync(0xFFFFFFFFu, cnt, o);
            if (cnt >= need) { T = mymax; cntT = cnt; break; }
            need -= cnt; bound = mymax - 1u;
        }
        if (cntT == need) {
            // fast path (virtually always): take all T-ties
            #pragma unroll
            for (int j = 0; j < 25; j++) {
                bool sel = (lane + 32 * j < NS) && (ukey[j] >= T);
                unsigned smask = __ballot_sync(0xFFFFFFFFu, sel);
                if (lane == 0) msel[c][j] = smask;
            }
        } else {
            int cum = 0;
            #pragma unroll
            for (int j = 0; j < 25; j++) {
                bool valid = (lane + 32 * j < NS);
                unsigned u = valid ? ukey[j] : (T ^ 1u);
                unsigned eqm = __ballot_sync(0xFFFFFFFFu, valid && (u == T));
                bool sel = valid && (u > T ||
                          (u == T && (cum + __popc(eqm & ((1u << lane) - 1u)) < need)));
                unsigned smask = __ballot_sync(0xFFFFFFFFu, sel);
                if (lane == 0) msel[c][j] = smask;
                cum += __popc(eqm);
            }
        }
    }
    __syncthreads();

    // ---- m[s] = sum_c (sel ? v : 0.7v);  c0[s] = sum_c sel ---------------
    const bool act = (tid < NS);
    float m = 0.f;
    if (act) {
        const long long xb = (long long)b * NC * NNtok * NNtok;
        const int jw = tid >> 5; const unsigned bit = 1u << (tid & 31);
        int cnt = 0;
        #pragma unroll
        for (int c = 0; c < NC; c++) {
            float v = x[xb + (long long)c * NNtok * NNtok + 1 + tid];  // L1-hot
            bool sel = (msel[c][jw] & bit) != 0u;
            m += sel ? v : v * SCL;
            cnt += sel ? 1 : 0;
        }
        msh[tid] = m;
        c0[tid]  = (unsigned char)cnt;
    }

    // ---- pass 1: mean + c+ + c- + (max m, argmax) simultaneously ---------
    {
        float p  = act ? m * (1.0f / NC) : 0.f;
        float ps = act ? m : 0.f;
        float cpv = (p > 0.f) ? p * p : 0.f;
        float cmv = (p < 0.f) ? p * p : 0.f;
        float bv = act ? m : -1e30f; int bi = act ? tid : NS;
        for (int o = 16; o; o >>= 1) {
            ps  += __shfl_xor_sync(0xFFFFFFFFu, ps,  o);
            cpv += __shfl_xor_sync(0xFFFFFFFFu, cpv, o);
            cmv += __shfl_xor_sync(0xFFFFFFFFu, cmv, o);
            float ov = __shfl_xor_sync(0xFFFFFFFFu, bv, o);
            int   oi = __shfl_xor_sync(0xFFFFFFFFu, bi, o);
            if (ov > bv || (ov == bv && oi < bi)) { bv = ov; bi = oi; }
        }
        if (lane == 0) {
            redf[warp] = ps; redf2[warp] = cpv; redf3[warp] = cmv;
            redf4[warp] = bv; redi[warp] = bi;
        }
        __syncthreads();
        if (warp == 0) {
            float a = redf[lane], c = redf2[lane], d = redf3[lane];
            float v = redf4[lane]; int i = redi[lane];
            for (int o = 16; o; o >>= 1) {
                a += __shfl_xor_sync(0xFFFFFFFFu, a, o);
                c += __shfl_xor_sync(0xFFFFFFFFu, c, o);
                d += __shfl_xor_sync(0xFFFFFFFFu, d, o);
                float ov = __shfl_xor_sync(0xFFFFFFFFu, v, o);
                int   oi = __shfl_xor_sync(0xFFFFFFFFu, i, o);
                if (ov > v || (ov == v && oi < i)) { v = ov; i = oi; }
            }
            if (lane == 0) {
                s_mean = a / (float)NS; s_cp = c; s_cm = d;
                s_maxm = v; s_anchor = i; s_pa = v * (1.0f / NC);
            }
        }
        __syncthreads();
    }
    // Fast path valid when max(m) > mean AND max(m) > 0; else exact masked argmax.
    if (!(s_maxm > s_mean && s_maxm > 0.f)) {
        float bv = -1e30f; int bi = NS;
        if (act) { float v = (m > s_mean) ? m * (1.0f / NC) : 0.0f; bv = v; bi = tid; }
        for (int o = 16; o; o >>= 1) {
            float ov = __shfl_xor_sync(0xFFFFFFFFu, bv, o);
            int   oi = __shfl_xor_sync(0xFFFFFFFFu, bi, o);
            if (ov > bv || (ov == bv && oi < bi)) { bv = ov; bi = oi; }
        }
        if (lane == 0) { redf[warp] = bv; redi[warp] = bi; }
        __syncthreads();
        if (warp == 0) {
            float v = redf[lane]; int i = redi[lane];
            for (int o = 16; o; o >>= 1) {
                float ov = __shfl_xor_sync(0xFFFFFFFFu, v, o);
                int   oi = __shfl_xor_sync(0xFFFFFFFFu, i, o);
                if (ov > v || (ov == v && oi < i)) { v = ov; i = oi; }
            }
            if (lane == 0) { s_anchor = i; s_pa = msh[i] * (1.0f / NC); }
        }
        __syncthreads();
    }
    const int anchor = s_anchor;
    const float ai = (float)(anchor / NH), aj = (float)(anchor % NH);

    // ---- pass 2: w0 = sum pw*dist, w1 = sum pw*ang -----------------------
    {
        float w0 = 0.f, w1s = 0.f;
        if (act) {
            float p   = m * (1.0f / NC);
            float rc0 = ((float)(tid / NH) - ai) / (float)NH;
            float rc1 = ((float)(tid % NH) - aj) / (float)NH;
            w0  = p * sqrtf(rc0 * rc0 + rc1 * rc1);
            w1s = p * (atan2f(rc1, rc0) * 0.3183098861837907f + 1.0f) * 0.5f;
        }
        for (int o = 16; o; o >>= 1) {
            w0  += __shfl_xor_sync(0xFFFFFFFFu, w0,  o);
            w1s += __shfl_xor_sync(0xFFFFFFFFu, w1s, o);
        }
        if (lane == 0) { redf[warp] = w0; redf4[warp] = w1s; }
        __syncthreads();
        if (warp == 0) {
            float a = redf[lane], bb = redf4[lane];
            for (int o = 16; o; o >>= 1) {
                a  += __shfl_xor_sync(0xFFFFFFFFu, a,  o);
                bb += __shfl_xor_sync(0xFFFFFFFFu, bb, o);
            }
            if (lane == 0) { s_w0 = a; s_w1 = bb; }
        }
        __syncthreads();
    }

    // ---- coef[k] = (u>0 ? cp : cm) * u  (cp*u+ - cm*u- collapses) --------
    if (tid < KHID) {
        float u = s_w0 * w1[tid] + s_w1 * w1[KHID + tid];
        scoef[tid] = u * (u > 0.f ? s_cp : s_cm);
    }

    // ---- 3x3 conv + per-warp value histogram -----------------------------
    int vcc = 0; unsigned mm;
    if (act) {
        int i0 = tid / NH, j0 = tid % NH;
        #pragma unroll
        for (int di = -1; di <= 1; di++)
            #pragma unroll
            for (int dj = -1; dj <= 1; dj++) {
                int ii = i0 + di, jj = j0 + dj;
                if (ii >= 0 && ii < NH && jj >= 0 && jj < NH)
                    vcc += (2 - abs(di)) * (2 - abs(dj)) * (int)c0[ii * NH + jj];
            }
    }
    {
        int key = act ? vcc : 999;
        mm = __match_any_sync(0xFFFFFFFFu, key);
        if (act && lane == (__ffs(mm) - 1))
            whist[warp][vcc] = (unsigned char)__popc(mm);
    }
    __syncthreads();

    // ---- sfx[v] = # strictly greater (suffix over 256 bins) --------------
    int sh = 0, ss = 0;
    if (tid < 256) {
        #pragma unroll
        for (int r = 0; r < NWA; r++) sh += (int)whist[r][tid];
        ss = sh;
        #pragma unroll
        for (int o = 1; o < 32; o <<= 1) {
            int n = __shfl_up_sync(0xFFFFFFFFu, ss, o);
            if (lane >= o) ss += n;
        }
        if (lane == 31) redi[tid >> 5] = ss;
    }
    __syncthreads();
    if (tid < 256) {
        int off = 0, total = 0;
        #pragma unroll
        for (int r = 0; r < 8; r++) {
            int w = redi[r]; total += w; if (r < (tid >> 5)) off += w;
        }
        sfx[tid] = total - (ss + off);
    }
    __syncthreads();

    // ---- stable descending ranks -> smem patch list ----------------------
    if (act) {
        int g = sfx[vcc];
        if (g < seln) {
            int e = __popc(mm & ((1u << lane) - 1u));
            for (int r = 0; r < warp; r++) e += (int)whist[r][vcc];
            int rk = g + e;                 // ties by ascending index (stable)
            if (rk < seln) spatch[rk] = (short)(tid + 1);
        }
    }

    // ---- GEMV split by sub: 24 col-groups x 32 k-chunks of 16 ------------
    if (tid < 768) {
        const int g  = tid % 24;            // 4 cols/group: cols sub*96+4g..
        const int ks = tid / 24;            // 0..31
        const float4* w4 = (const float4*)w2 + sub * 24 + g;
        float4 acc = make_float4(0.f, 0.f, 0.f, 0.f);
        #pragma unroll 16
        for (int k = ks * 16; k < ks * 16 + 16; k++) {
            float c = scoef[k];
            float4 w = __ldg(w4 + (size_t)k * (ND / 4));
            acc.x += c * w.x; acc.y += c * w.y; acc.z += c * w.z; acc.w += c * w.w;
        }
        gp4[tid] = acc;
    }
    __syncthreads();
    if (tid < 24) {
        float4 v = make_float4(0.f, 0.f, 0.f, 0.f);
        #pragma unroll
        for (int r = 0; r < 32; r++) {
            float4 a = gp4[r * 24 + tid];
            v.x += a.x; v.y += a.y; v.z += a.z; v.w += a.w;
        }
        v.x *= s_pa; v.y *= s_pa; v.z *= s_pa; v.w *= s_pa;
        v.x = v.x > 0.f ? v.x : 0.2f * v.x;
        v.y = v.y > 0.f ? v.y : 0.2f * v.y;
        v.z = v.z > 0.f ? v.z : 0.2f * v.z;
        v.w = v.w > 0.f ? v.w : 0.2f * v.w;
        const int fi4 = b * NNtok * (ND / 4) + sub * 24 + tid;   // row 0
        float4 h4 = ((const float4*)hs)[fi4];
        v.x += h4.x; v.y += h4.y; v.z += h4.z; v.w += h4.w;
        ((float4*)out)[fi4] = v;
    }

    // ---- gather: rows q = sub, sub+8, ... --------------------------------
    {
        const float4* hin = (const float4*)hs;
        float4* o4 = (float4*)out;
        const int nh = (seln - sub + 7) / 8;               // # rows we own
        const int tot = nh * (ND / 4);
        for (int t = tid; t < tot; t += TPB) {
            int r  = t / (ND / 4);
            int d4 = t - r * (ND / 4);
            int q  = 8 * r + sub;
            int p  = (int)spatch[q];       // in [1,784]: unmodified hs rows
            o4[NB * NNtok * (ND / 4) + (b * seln + q) * (ND / 4) + d4] =
                hin[(b * NNtok + p) * (ND / 4) + d4];
        }
    }
}

// ---------------- launch ----------------
extern "C" void kernel_launch(void* const* d_in, const int* in_sizes, int n_in,
                              void* d_out, int out_size)
{
    const float* hs = (const float*)d_in[0];
    const float* x  = (const float*)d_in[1];
    const float* w1 = (const float*)d_in[2];
    const float* w2 = (const float*)d_in[3];

    const int hs_elems = NB * NNtok * ND;
    int seln = (out_size - hs_elems) / (NB * ND);
    if (seln < 1) seln = 1;
    if (seln > NS) seln = NS;

    kAll<<<NCB + NCPB, TPB>>>(x, w1, w2, hs, (float*)d_out, seln);
}